// round 4
// baseline (speedup 1.0000x reference)
#include <cuda_runtime.h>
#include <cstdint>

#define MARGIN 0.3f
#define EPSV   1e-6f

#define MAX_B 8192
#define MAX_L 4096
#define INF_I 0x7fffffff

__device__ int2  g_pair[MAX_B];     // per-anchor {pos_idx, neg_idx} (INF_I = none)
__device__ float g_loss[MAX_B];     // per-anchor triplet loss
__device__ int   g_valid[MAX_B];    // per-anchor validity
__device__ int   g_done;            // completion ticket for tail reduction

__device__ __forceinline__ int read_label(const void* lab, int i, int is64) {
    if (is64) return (int)((const long long*)lab)[i];
    return ((const int*)lab)[i];
}

// ================================================================ kernel A
// One block. Shared-memory label tables; resolves per-anchor pos/neg indices.
__global__ void k_labels(const void* __restrict__ labels, int B) {
    __shared__ int s_min1[MAX_L];
    __shared__ int s_min2[MAX_L];
    __shared__ int s_flag;   // any nonzero odd 32-bit word -> labels are int32
    __shared__ int s_diff;   // first index whose label != labels[0]
    int t = threadIdx.x;
    int nt = blockDim.x;

    for (int j = t; j < MAX_L; j += nt) { s_min1[j] = INF_I; s_min2[j] = INF_I; }
    if (t == 0) { s_flag = 0; s_diff = INF_I; g_done = 0; }
    __syncthreads();

    // dtype detect: odd word indices < B are the high halves of int64 labels
    // (all zero for labels < 2^32) or independent int32 labels (never all zero).
    const int* w = (const int*)labels;
    for (int i = 2 * t + 1; i < B; i += 2 * nt)
        if (w[i] != 0) atomicOr(&s_flag, 1);
    __syncthreads();
    int is64 = (s_flag == 0);
    int l0 = read_label(labels, 0, is64);

    // pass 1: first occurrence per label; first differing index
    for (int i = t; i < B; i += nt) {
        int li = read_label(labels, i, is64);
        if (li >= 0 && li < MAX_L) atomicMin(&s_min1[li], i);
        if (li != l0) atomicMin(&s_diff, i);
    }
    __syncthreads();

    // pass 2: second occurrence per label
    for (int i = t; i < B; i += nt) {
        int li = read_label(labels, i, is64);
        if (li >= 0 && li < MAX_L && s_min1[li] != i) atomicMin(&s_min2[li], i);
    }
    __syncthreads();

    // resolve per-anchor pos/neg
    for (int i = t; i < B; i += nt) {
        int li = read_label(labels, i, is64);
        int p = (li >= 0 && li < MAX_L) ? s_min1[li] : INF_I;
        if (p == i) p = s_min2[li];
        int n = (li != l0) ? 0 : s_diff;
        g_pair[i] = make_int2(p, n);
    }
}

// ================================================================ kernel B
// Warp per anchor, register-batched loads for max MLP, fused tail reduction.
__global__ void __launch_bounds__(256, 2)
k_dist(const float* __restrict__ features, float* __restrict__ out, int B, int D) {
    __shared__ int s_ticket;
    int warp = (blockIdx.x * blockDim.x + threadIdx.x) >> 5;
    int lane = threadIdx.x & 31;

    if (warp < B) {
        int2 pn = g_pair[warp];
        if (pn.x != INF_I && pn.y != INF_I) {
            const float4* __restrict__ A = (const float4*)(features + (size_t)warp * D);
            const float4* __restrict__ P = (const float4*)(features + (size_t)pn.x * D);
            const float4* __restrict__ N = (const float4*)(features + (size_t)pn.y * D);
            float sap = 0.0f, san = 0.0f;

            if (D == 1024) {
                // Fast path: batch all 24 LDG.128 before any FMA (MLP ~= 24).
                float4 a[8], p4[8], n4[8];
                #pragma unroll
                for (int k = 0; k < 8; k++) a[k]  = A[lane + 32 * k];
                #pragma unroll
                for (int k = 0; k < 8; k++) p4[k] = P[lane + 32 * k];
                #pragma unroll
                for (int k = 0; k < 8; k++) n4[k] = N[lane + 32 * k];
                #pragma unroll
                for (int k = 0; k < 8; k++) {
                    float d;
                    d = a[k].x - p4[k].x + EPSV; sap = fmaf(d, d, sap);
                    d = a[k].y - p4[k].y + EPSV; sap = fmaf(d, d, sap);
                    d = a[k].z - p4[k].z + EPSV; sap = fmaf(d, d, sap);
                    d = a[k].w - p4[k].w + EPSV; sap = fmaf(d, d, sap);
                    d = a[k].x - n4[k].x + EPSV; san = fmaf(d, d, san);
                    d = a[k].y - n4[k].y + EPSV; san = fmaf(d, d, san);
                    d = a[k].z - n4[k].z + EPSV; san = fmaf(d, d, san);
                    d = a[k].w - n4[k].w + EPSV; san = fmaf(d, d, san);
                }
            } else {
                int nv = D >> 2;
                for (int k = lane; k < nv; k += 32) {
                    float4 a = A[k], pp = P[k], nn = N[k];
                    float d;
                    d = a.x - pp.x + EPSV; sap = fmaf(d, d, sap);
                    d = a.y - pp.y + EPSV; sap = fmaf(d, d, sap);
                    d = a.z - pp.z + EPSV; sap = fmaf(d, d, sap);
                    d = a.w - pp.w + EPSV; sap = fmaf(d, d, sap);
                    d = a.x - nn.x + EPSV; san = fmaf(d, d, san);
                    d = a.y - nn.y + EPSV; san = fmaf(d, d, san);
                    d = a.z - nn.z + EPSV; san = fmaf(d, d, san);
                    d = a.w - nn.w + EPSV; san = fmaf(d, d, san);
                }
            }
            #pragma unroll
            for (int off = 16; off > 0; off >>= 1) {
                sap += __shfl_down_sync(0xffffffffu, sap, off);
                san += __shfl_down_sync(0xffffffffu, san, off);
            }
            if (lane == 0) {
                g_loss[warp]  = fmaxf(sqrtf(sap) - sqrtf(san) + MARGIN, 0.0f);
                g_valid[warp] = 1;
            }
        } else if (lane == 0) {
            g_loss[warp] = 0.0f;
            g_valid[warp] = 0;
        }
    }

    // ---- last-block-done deterministic reduction (single fence per block) ----
    __syncthreads();
    if (threadIdx.x == 0) {
        __threadfence();                      // drains this SM's outstanding stores
        s_ticket = atomicAdd(&g_done, 1);
    }
    __syncthreads();
    if (s_ticket != (int)gridDim.x - 1) return;

    __shared__ float s_sum[256];
    __shared__ int   s_cnt[256];
    int t = threadIdx.x;
    float sum = 0.0f;
    int cnt = 0;
    for (int i = t; i < B; i += blockDim.x) {
        sum += __ldcg(&g_loss[i]);            // L1-bypass: other SMs' writes live in L2
        cnt += __ldcg(&g_valid[i]);
    }
    s_sum[t] = sum;
    s_cnt[t] = cnt;
    __syncthreads();
    for (int off = (int)blockDim.x >> 1; off > 0; off >>= 1) {
        if (t < off) {
            s_sum[t] += s_sum[t + off];
            s_cnt[t] += s_cnt[t + off];
        }
        __syncthreads();
    }
    if (t == 0) {
        int c = s_cnt[0];
        out[0] = (c > 0) ? (s_sum[0] / (float)c) : 0.0f;
    }
}

// ================================================================ launch
extern "C" void kernel_launch(void* const* d_in, const int* in_sizes, int n_in,
                              void* d_out, int out_size) {
    int i_feat = (in_sizes[0] >= in_sizes[1]) ? 0 : 1;
    int i_lab  = 1 - i_feat;
    const float* features = (const float*)d_in[i_feat];
    const void*  labels   = d_in[i_lab];
    int B = in_sizes[i_lab];
    int D = in_sizes[i_feat] / B;

    k_labels<<<1, 1024>>>(labels, B);
    k_dist  <<<(B + 7) / 8, 256>>>(features, (float*)d_out, B, D);
}

// round 5
// speedup vs baseline: 1.4756x; 1.4756x over previous
#include <cuda_runtime.h>
#include <cstdint>

#define MARGIN 0.3f
#define EPSV   1e-6f

#define MAX_B 8192
#define MAX_L 4096
#define INF_I 0x7fffffff

__device__ int2  g_pair[MAX_B];     // per-anchor {pos_idx, neg_idx} (INF_I = none)
__device__ float g_loss[MAX_B];     // per-anchor triplet loss
__device__ int   g_valid[MAX_B];    // per-anchor validity

__device__ __forceinline__ int read_label(const void* lab, int i, int is64) {
    if (is64) return (int)((const long long*)lab)[i];
    return ((const int*)lab)[i];
}

// ================================================================ kernel A
// One block. Shared-memory label tables; resolves per-anchor pos/neg indices.
__global__ void k_labels(const void* __restrict__ labels, int B) {
    __shared__ int s_min1[MAX_L];
    __shared__ int s_min2[MAX_L];
    __shared__ int s_flag;   // any nonzero odd 32-bit word -> labels are int32
    __shared__ int s_diff;   // first index whose label != labels[0]
    int t = threadIdx.x;
    int nt = blockDim.x;

    for (int j = t; j < MAX_L; j += nt) { s_min1[j] = INF_I; s_min2[j] = INF_I; }
    if (t == 0) { s_flag = 0; s_diff = INF_I; }
    __syncthreads();

    // dtype detect: odd word indices < B are the high halves of int64 labels
    // (all zero for labels < 2^32) or independent int32 labels (never all zero).
    const int* w = (const int*)labels;
    for (int i = 2 * t + 1; i < B; i += 2 * nt)
        if (w[i] != 0) atomicOr(&s_flag, 1);
    __syncthreads();
    int is64 = (s_flag == 0);
    int l0 = read_label(labels, 0, is64);

    // pass 1: first occurrence per label; first differing index
    for (int i = t; i < B; i += nt) {
        int li = read_label(labels, i, is64);
        if (li >= 0 && li < MAX_L) atomicMin(&s_min1[li], i);
        if (li != l0) atomicMin(&s_diff, i);
    }
    __syncthreads();

    // pass 2: second occurrence per label
    for (int i = t; i < B; i += nt) {
        int li = read_label(labels, i, is64);
        if (li >= 0 && li < MAX_L && s_min1[li] != i) atomicMin(&s_min2[li], i);
    }
    __syncthreads();

    // resolve per-anchor pos/neg
    for (int i = t; i < B; i += nt) {
        int li = read_label(labels, i, is64);
        int p = (li >= 0 && li < MAX_L) ? s_min1[li] : INF_I;
        if (p == i) p = s_min2[li];
        int n = (li != l0) ? 0 : s_diff;
        g_pair[i] = make_int2(p, n);
    }
}

// ================================================================ kernel B
// Warp per anchor, 2-stage software pipeline. NO tail fusion, NO atomics.
__global__ void k_dist(const float* __restrict__ features, int B, int D) {
    int warp = (blockIdx.x * blockDim.x + threadIdx.x) >> 5;
    int lane = threadIdx.x & 31;
    if (warp >= B) return;

    int2 pn = g_pair[warp];
    if (pn.x == INF_I || pn.y == INF_I) {
        if (lane == 0) { g_loss[warp] = 0.0f; g_valid[warp] = 0; }
        return;
    }

    const float4* __restrict__ A = (const float4*)(features + (size_t)warp * D);
    const float4* __restrict__ P = (const float4*)(features + (size_t)pn.x * D);
    const float4* __restrict__ N = (const float4*)(features + (size_t)pn.y * D);
    float sap = 0.0f, san = 0.0f;

    if (D == 1024) {
        // 8 iterations of 3 float4 loads, pipelined one stage ahead.
        float4 a  = __ldcs(&A[lane]);        // anchor: streaming (read-once)
        float4 pp = P[lane];
        float4 nn = N[lane];
        #pragma unroll
        for (int k = 1; k <= 8; k++) {
            float4 a2, p2, n2;
            if (k < 8) {
                a2 = __ldcs(&A[lane + 32 * k]);
                p2 = P[lane + 32 * k];
                n2 = N[lane + 32 * k];
            }
            float d;
            d = a.x - pp.x + EPSV; sap = fmaf(d, d, sap);
            d = a.y - pp.y + EPSV; sap = fmaf(d, d, sap);
            d = a.z - pp.z + EPSV; sap = fmaf(d, d, sap);
            d = a.w - pp.w + EPSV; sap = fmaf(d, d, sap);
            d = a.x - nn.x + EPSV; san = fmaf(d, d, san);
            d = a.y - nn.y + EPSV; san = fmaf(d, d, san);
            d = a.z - nn.z + EPSV; san = fmaf(d, d, san);
            d = a.w - nn.w + EPSV; san = fmaf(d, d, san);
            a = a2; pp = p2; nn = n2;
        }
    } else {
        int nv = D >> 2;
        for (int k = lane; k < nv; k += 32) {
            float4 a = A[k], pp = P[k], nn = N[k];
            float d;
            d = a.x - pp.x + EPSV; sap = fmaf(d, d, sap);
            d = a.y - pp.y + EPSV; sap = fmaf(d, d, sap);
            d = a.z - pp.z + EPSV; sap = fmaf(d, d, sap);
            d = a.w - pp.w + EPSV; sap = fmaf(d, d, sap);
            d = a.x - nn.x + EPSV; san = fmaf(d, d, san);
            d = a.y - nn.y + EPSV; san = fmaf(d, d, san);
            d = a.z - nn.z + EPSV; san = fmaf(d, d, san);
            d = a.w - nn.w + EPSV; san = fmaf(d, d, san);
        }
    }
    #pragma unroll
    for (int off = 16; off > 0; off >>= 1) {
        sap += __shfl_down_sync(0xffffffffu, sap, off);
        san += __shfl_down_sync(0xffffffffu, san, off);
    }
    if (lane == 0) {
        g_loss[warp]  = fmaxf(sqrtf(sap) - sqrtf(san) + MARGIN, 0.0f);
        g_valid[warp] = 1;
    }
}

// ================================================================ kernel C
// Deterministic single-block reduction (kernel boundary = full ordering).
__global__ void k_reduce(float* __restrict__ out, int B) {
    __shared__ float s_sum[1024];
    __shared__ int   s_cnt[1024];
    int t = threadIdx.x;
    float sum = 0.0f;
    int cnt = 0;
    for (int i = t; i < B; i += blockDim.x) {
        sum += g_loss[i];
        cnt += g_valid[i];
    }
    s_sum[t] = sum;
    s_cnt[t] = cnt;
    __syncthreads();
    for (int off = (int)blockDim.x >> 1; off > 0; off >>= 1) {
        if (t < off) {
            s_sum[t] += s_sum[t + off];
            s_cnt[t] += s_cnt[t + off];
        }
        __syncthreads();
    }
    if (t == 0) {
        int c = s_cnt[0];
        out[0] = (c > 0) ? (s_sum[0] / (float)c) : 0.0f;
    }
}

// ================================================================ launch
extern "C" void kernel_launch(void* const* d_in, const int* in_sizes, int n_in,
                              void* d_out, int out_size) {
    int i_feat = (in_sizes[0] >= in_sizes[1]) ? 0 : 1;
    int i_lab  = 1 - i_feat;
    const float* features = (const float*)d_in[i_feat];
    const void*  labels   = d_in[i_lab];
    int B = in_sizes[i_lab];
    int D = in_sizes[i_feat] / B;

    k_labels<<<1, 1024>>>(labels, B);
    k_dist  <<<(B + 7) / 8, 256>>>(features, B, D);
    k_reduce<<<1, 1024>>>((float*)d_out, B);
}

// round 6
// speedup vs baseline: 1.5273x; 1.0351x over previous
#include <cuda_runtime.h>
#include <cstdint>

#define MARGIN 0.3f
#define EPSV   1e-6f

#define MAX_B 8192
#define MAX_L 1024
#define INF_I 0x7fffffff

__device__ int2  g_pair[MAX_B];     // per-anchor {pos_idx, neg_idx} (INF_I = none)
__device__ float g_loss[MAX_B];     // per-anchor loss; -1.0f = invalid anchor

__device__ __forceinline__ int read_label(const void* lab, int i, int is64) {
    if (is64) return (int)((const long long*)lab)[i];
    return ((const int*)lab)[i];
}

// ================================================================ kernel A
// One block. Labels cached in smem once; all passes run out of smem.
__global__ void k_labels(const void* __restrict__ labels, int B) {
    __shared__ int s_lab[MAX_B];    // cached label values (32 KB)
    __shared__ int s_min1[MAX_L];   // first occurrence per label
    __shared__ int s_min2[MAX_L];   // second occurrence per label
    __shared__ int s_flag;          // nonzero odd word -> labels are int32
    __shared__ int s_diff;          // first index with label != labels[0]
    int t = threadIdx.x;
    int nt = blockDim.x;

    for (int j = t; j < MAX_L; j += nt) { s_min1[j] = INF_I; s_min2[j] = INF_I; }
    if (t == 0) { s_flag = 0; s_diff = INF_I; }
    __syncthreads();

    // dtype detect: odd 32-bit words < B are high halves of int64 labels
    // (zero for labels < 2^32) or independent int32 labels (never all zero).
    const int* w = (const int*)labels;
    {
        int any = 0;
        for (int i = 2 * t + 1; i < B; i += 2 * nt) any |= w[i];
        if (any) atomicOr(&s_flag, 1);
    }
    __syncthreads();
    int is64 = (s_flag == 0);

    // single global pass: cache all labels into smem
    for (int i = t; i < B; i += nt) s_lab[i] = read_label(labels, i, is64);
    __syncthreads();
    int l0 = s_lab[0];

    // pass 1 (smem): first occurrence per label; first differing index
    for (int i = t; i < B; i += nt) {
        int li = s_lab[i];
        if ((unsigned)li < MAX_L) atomicMin(&s_min1[li], i);
        if (li != l0) atomicMin(&s_diff, i);
    }
    __syncthreads();

    // pass 2 (smem): second occurrence per label
    for (int i = t; i < B; i += nt) {
        int li = s_lab[i];
        if ((unsigned)li < MAX_L && s_min1[li] != i) atomicMin(&s_min2[li], i);
    }
    __syncthreads();

    // resolve per-anchor pos/neg
    for (int i = t; i < B; i += nt) {
        int li = s_lab[i];
        int p = ((unsigned)li < MAX_L) ? s_min1[li] : INF_I;
        if (p == i) p = s_min2[li];
        int n = (li != l0) ? 0 : s_diff;
        g_pair[i] = make_int2(p, n);
    }
}

// ================================================================ kernel B
// Warp per anchor, 2-stage software pipeline.
__global__ void k_dist(const float* __restrict__ features, int B, int D) {
    int warp = (blockIdx.x * blockDim.x + threadIdx.x) >> 5;
    int lane = threadIdx.x & 31;
    if (warp >= B) return;

    int2 pn = g_pair[warp];
    if (pn.x == INF_I || pn.y == INF_I) {
        if (lane == 0) g_loss[warp] = -1.0f;   // invalid sentinel
        return;
    }

    const float4* __restrict__ A = (const float4*)(features + (size_t)warp * D);
    const float4* __restrict__ P = (const float4*)(features + (size_t)pn.x * D);
    const float4* __restrict__ N = (const float4*)(features + (size_t)pn.y * D);
    float sap = 0.0f, san = 0.0f;

    if (D == 1024) {
        float4 a  = __ldcs(&A[lane]);          // anchor: streaming (read-once)
        float4 pp = P[lane];
        float4 nn = N[lane];
        #pragma unroll
        for (int k = 1; k <= 8; k++) {
            float4 a2, p2, n2;
            if (k < 8) {
                a2 = __ldcs(&A[lane + 32 * k]);
                p2 = P[lane + 32 * k];
                n2 = N[lane + 32 * k];
            }
            float d;
            d = a.x - pp.x + EPSV; sap = fmaf(d, d, sap);
            d = a.y - pp.y + EPSV; sap = fmaf(d, d, sap);
            d = a.z - pp.z + EPSV; sap = fmaf(d, d, sap);
            d = a.w - pp.w + EPSV; sap = fmaf(d, d, sap);
            d = a.x - nn.x + EPSV; san = fmaf(d, d, san);
            d = a.y - nn.y + EPSV; san = fmaf(d, d, san);
            d = a.z - nn.z + EPSV; san = fmaf(d, d, san);
            d = a.w - nn.w + EPSV; san = fmaf(d, d, san);
            a = a2; pp = p2; nn = n2;
        }
    } else {
        int nv = D >> 2;
        for (int k = lane; k < nv; k += 32) {
            float4 a = A[k], pp = P[k], nn = N[k];
            float d;
            d = a.x - pp.x + EPSV; sap = fmaf(d, d, sap);
            d = a.y - pp.y + EPSV; sap = fmaf(d, d, sap);
            d = a.z - pp.z + EPSV; sap = fmaf(d, d, sap);
            d = a.w - pp.w + EPSV; sap = fmaf(d, d, sap);
            d = a.x - nn.x + EPSV; san = fmaf(d, d, san);
            d = a.y - nn.y + EPSV; san = fmaf(d, d, san);
            d = a.z - nn.z + EPSV; san = fmaf(d, d, san);
            d = a.w - nn.w + EPSV; san = fmaf(d, d, san);
        }
    }
    #pragma unroll
    for (int off = 16; off > 0; off >>= 1) {
        sap += __shfl_down_sync(0xffffffffu, sap, off);
        san += __shfl_down_sync(0xffffffffu, san, off);
    }
    if (lane == 0)
        g_loss[warp] = fmaxf(sqrtf(sap) - sqrtf(san) + MARGIN, 0.0f);
}

// ================================================================ kernel C
// Deterministic single-block reduction over one array (-1 = invalid).
__global__ void k_reduce(float* __restrict__ out, int B) {
    __shared__ float s_sum[1024];
    __shared__ int   s_cnt[1024];
    int t = threadIdx.x;
    float sum = 0.0f;
    int cnt = 0;
    for (int i = t; i < B; i += blockDim.x) {
        float v = g_loss[i];
        if (v >= 0.0f) { sum += v; cnt++; }
    }
    s_sum[t] = sum;
    s_cnt[t] = cnt;
    __syncthreads();
    for (int off = (int)blockDim.x >> 1; off > 0; off >>= 1) {
        if (t < off) {
            s_sum[t] += s_sum[t + off];
            s_cnt[t] += s_cnt[t + off];
        }
        __syncthreads();
    }
    if (t == 0) {
        int c = s_cnt[0];
        out[0] = (c > 0) ? (s_sum[0] / (float)c) : 0.0f;
    }
}

// ================================================================ launch
extern "C" void kernel_launch(void* const* d_in, const int* in_sizes, int n_in,
                              void* d_out, int out_size) {
    int i_feat = (in_sizes[0] >= in_sizes[1]) ? 0 : 1;
    int i_lab  = 1 - i_feat;
    const float* features = (const float*)d_in[i_feat];
    const void*  labels   = d_in[i_lab];
    int B = in_sizes[i_lab];
    int D = in_sizes[i_feat] / B;

    k_labels<<<1, 1024>>>(labels, B);
    k_dist  <<<(B + 7) / 8, 256>>>(features, B, D);
    k_reduce<<<1, 1024>>>((float*)d_out, B);
}

// round 7
// speedup vs baseline: 1.5447x; 1.0113x over previous
#include <cuda_runtime.h>
#include <cstdint>

#define MARGIN 0.3f
#define EPSV   1e-6f

#define MAX_B 8192
#define MAX_L 1024
#define INF_I 0x7fffffff

__device__ int2  g_pair[MAX_B];     // per-anchor {pos_idx, neg_idx} (INF_I = none)
__device__ float g_loss[MAX_B];     // per-anchor loss; -1.0f = invalid anchor

__device__ __forceinline__ int read_label(const void* lab, int i, int is64) {
    if (is64) return (int)((const long long*)lab)[i];
    return ((const int*)lab)[i];
}

// ================================================================ kernel A
// One block. Labels cached in smem; single-address atomics warp-aggregated.
__global__ void k_labels(const void* __restrict__ labels, int B) {
    __shared__ int s_lab[MAX_B];    // cached decoded labels (32 KB)
    __shared__ int s_min1[MAX_L];   // first occurrence per label
    __shared__ int s_min2[MAX_L];   // second occurrence per label
    __shared__ int s_flag;          // nonzero odd word -> labels are int32
    __shared__ int s_diff;          // first index with label != labels[0]
    int t = threadIdx.x;
    int nt = blockDim.x;
    int lane = t & 31;

    for (int j = t; j < MAX_L; j += nt) { s_min1[j] = INF_I; s_min2[j] = INF_I; }
    if (t == 0) { s_flag = 0; s_diff = INF_I; }
    __syncthreads();

    // dtype detect: odd 32-bit words < B are high halves of int64 labels
    // (zero for labels < 2^32) or independent int32 labels (never all zero).
    // Warp-aggregated: one ballot + at most one atomic per warp.
    {
        const int* w = (const int*)labels;
        int any = 0;
        for (int i = 2 * t + 1; i < B; i += 2 * nt) any |= w[i];
        if (__any_sync(0xffffffffu, any != 0) && lane == 0) atomicOr(&s_flag, 1);
    }
    __syncthreads();
    int is64 = (s_flag == 0);

    // decode labels into smem (single global pass)
    for (int i = t; i < B; i += nt) s_lab[i] = read_label(labels, i, is64);
    __syncthreads();
    int l0 = s_lab[0];

    // pass 1: first occurrence per label (spread atomics, near LSU floor);
    // first-differing-index via private candidate + one warp-reduced atomic.
    {
        int cand = INF_I;
        for (int i = t; i < B; i += nt) {
            int li = s_lab[i];
            if ((unsigned)li < MAX_L) atomicMin(&s_min1[li], i);
            if (li != l0 && i < cand) cand = i;
        }
        #pragma unroll
        for (int off = 16; off > 0; off >>= 1)
            cand = min(cand, __shfl_down_sync(0xffffffffu, cand, off));
        if (lane == 0 && cand != INF_I) atomicMin(&s_diff, cand);
    }
    __syncthreads();

    // pass 2: second occurrence per label
    for (int i = t; i < B; i += nt) {
        int li = s_lab[i];
        if ((unsigned)li < MAX_L && s_min1[li] != i) atomicMin(&s_min2[li], i);
    }
    __syncthreads();

    // resolve per-anchor pos/neg
    int d0 = s_diff;
    for (int i = t; i < B; i += nt) {
        int li = s_lab[i];
        int p = ((unsigned)li < MAX_L) ? s_min1[li] : INF_I;
        if (p == i) p = s_min2[li];
        int n = (li != l0) ? 0 : d0;
        g_pair[i] = make_int2(p, n);
    }
}

// ================================================================ kernel B
// Warp per anchor, 2-stage software pipeline.
__global__ void k_dist(const float* __restrict__ features, int B, int D) {
    int warp = (blockIdx.x * blockDim.x + threadIdx.x) >> 5;
    int lane = threadIdx.x & 31;
    if (warp >= B) return;

    int2 pn = g_pair[warp];
    if (pn.x == INF_I || pn.y == INF_I) {
        if (lane == 0) g_loss[warp] = -1.0f;   // invalid sentinel
        return;
    }

    const float4* __restrict__ A = (const float4*)(features + (size_t)warp * D);
    const float4* __restrict__ P = (const float4*)(features + (size_t)pn.x * D);
    const float4* __restrict__ N = (const float4*)(features + (size_t)pn.y * D);
    float sap = 0.0f, san = 0.0f;

    if (D == 1024) {
        float4 a  = __ldcs(&A[lane]);          // anchor: streaming (read-once)
        float4 pp = P[lane];
        float4 nn = N[lane];
        #pragma unroll
        for (int k = 1; k <= 8; k++) {
            float4 a2, p2, n2;
            if (k < 8) {
                a2 = __ldcs(&A[lane + 32 * k]);
                p2 = P[lane + 32 * k];
                n2 = N[lane + 32 * k];
            }
            float d;
            d = a.x - pp.x + EPSV; sap = fmaf(d, d, sap);
            d = a.y - pp.y + EPSV; sap = fmaf(d, d, sap);
            d = a.z - pp.z + EPSV; sap = fmaf(d, d, sap);
            d = a.w - pp.w + EPSV; sap = fmaf(d, d, sap);
            d = a.x - nn.x + EPSV; san = fmaf(d, d, san);
            d = a.y - nn.y + EPSV; san = fmaf(d, d, san);
            d = a.z - nn.z + EPSV; san = fmaf(d, d, san);
            d = a.w - nn.w + EPSV; san = fmaf(d, d, san);
            a = a2; pp = p2; nn = n2;
        }
    } else {
        int nv = D >> 2;
        for (int k = lane; k < nv; k += 32) {
            float4 a = A[k], pp = P[k], nn = N[k];
            float d;
            d = a.x - pp.x + EPSV; sap = fmaf(d, d, sap);
            d = a.y - pp.y + EPSV; sap = fmaf(d, d, sap);
            d = a.z - pp.z + EPSV; sap = fmaf(d, d, sap);
            d = a.w - pp.w + EPSV; sap = fmaf(d, d, sap);
            d = a.x - nn.x + EPSV; san = fmaf(d, d, san);
            d = a.y - nn.y + EPSV; san = fmaf(d, d, san);
            d = a.z - nn.z + EPSV; san = fmaf(d, d, san);
            d = a.w - nn.w + EPSV; san = fmaf(d, d, san);
        }
    }
    #pragma unroll
    for (int off = 16; off > 0; off >>= 1) {
        sap += __shfl_down_sync(0xffffffffu, sap, off);
        san += __shfl_down_sync(0xffffffffu, san, off);
    }
    if (lane == 0)
        g_loss[warp] = fmaxf(sqrtf(sap) - sqrtf(san) + MARGIN, 0.0f);
}

// ================================================================ kernel C
// Deterministic single-block reduction over one array (-1 = invalid).
__global__ void k_reduce(float* __restrict__ out, int B) {
    __shared__ float s_sum[1024];
    __shared__ int   s_cnt[1024];
    int t = threadIdx.x;
    float sum = 0.0f;
    int cnt = 0;
    for (int i = t; i < B; i += blockDim.x) {
        float v = g_loss[i];
        if (v >= 0.0f) { sum += v; cnt++; }
    }
    s_sum[t] = sum;
    s_cnt[t] = cnt;
    __syncthreads();
    for (int off = (int)blockDim.x >> 1; off > 0; off >>= 1) {
        if (t < off) {
            s_sum[t] += s_sum[t + off];
            s_cnt[t] += s_cnt[t + off];
        }
        __syncthreads();
    }
    if (t == 0) {
        int c = s_cnt[0];
        out[0] = (c > 0) ? (s_sum[0] / (float)c) : 0.0f;
    }
}

// ================================================================ launch
extern "C" void kernel_launch(void* const* d_in, const int* in_sizes, int n_in,
                              void* d_out, int out_size) {
    int i_feat = (in_sizes[0] >= in_sizes[1]) ? 0 : 1;
    int i_lab  = 1 - i_feat;
    const float* features = (const float*)d_in[i_feat];
    const void*  labels   = d_in[i_lab];
    int B = in_sizes[i_lab];
    int D = in_sizes[i_feat] / B;

    k_labels<<<1, 1024>>>(labels, B);
    k_dist  <<<(B + 7) / 8, 256>>>(features, B, D);
    k_reduce<<<1, 1024>>>((float*)d_out, B);
}